// round 1
// baseline (speedup 1.0000x reference)
#include <cuda_runtime.h>

// Problem constants
constexpr int Bc   = 2;
constexpr int Sc   = 2048;
constexpr int HIDc = 1024;
constexpr int NHc  = 16;
constexpr int HDc  = 64;           // HID / NH
constexpr int Mtot = Bc * Sc;      // 4096
constexpr size_t CHUNK = (size_t)Bc * Sc * HIDc;  // 4,194,304 floats

// Scratch: [0]=Q, [1]=K, [2]=V, [3]=ctx (attn @ V, in [B,S,HID] layout)
__device__ float g_buf[4 * CHUNK];

// ---------------------------------------------------------------------------
// SGEMM NT + bias: C[m,n] = sum_k A[m,k] * W[n,k] + bias[n]
// BM=128, BN=128, BK=8, 256 threads, 8x8 per thread.
// a_sel / c_sel >= 0 selects a g_buf chunk instead of the external pointer.
// ---------------------------------------------------------------------------
__global__ __launch_bounds__(256) void sgemm_nt_bias(
    const float* __restrict__ Aext, int a_sel,
    const float* __restrict__ W, const float* __restrict__ bias,
    float* __restrict__ Cext, int c_sel,
    int M, int N, int K)
{
    const float* A = (a_sel >= 0) ? (const float*)(g_buf + (size_t)a_sel * CHUNK) : Aext;
    float*       C = (c_sel >= 0) ? (g_buf + (size_t)c_sel * CHUNK) : Cext;

    constexpr int BM = 128, BN = 128, BK = 8, TM = 8, TN = 8;
    __shared__ float As[BK][BM + 4];
    __shared__ float Ws[BK][BN + 4];

    const int tid = threadIdx.x;
    const int tx = tid & 15, ty = tid >> 4;
    const int bm = blockIdx.y * BM, bn = blockIdx.x * BN;

    const int lrow = tid >> 1;        // 0..127
    const int lcol = (tid & 1) * 4;   // 0 or 4
    const float* Ap = A + (size_t)(bm + lrow) * K + lcol;
    const float* Wp = W + (size_t)(bn + lrow) * K + lcol;

    float acc[TM][TN];
    #pragma unroll
    for (int i = 0; i < TM; i++)
        #pragma unroll
        for (int j = 0; j < TN; j++) acc[i][j] = 0.0f;

    for (int k0 = 0; k0 < K; k0 += BK) {
        float4 av = *(const float4*)(Ap + k0);
        float4 wv = *(const float4*)(Wp + k0);
        As[lcol + 0][lrow] = av.x; As[lcol + 1][lrow] = av.y;
        As[lcol + 2][lrow] = av.z; As[lcol + 3][lrow] = av.w;
        Ws[lcol + 0][lrow] = wv.x; Ws[lcol + 1][lrow] = wv.y;
        Ws[lcol + 2][lrow] = wv.z; Ws[lcol + 3][lrow] = wv.w;
        __syncthreads();
        #pragma unroll
        for (int kk = 0; kk < BK; kk++) {
            float a[TM], b[TN];
            *(float4*)&a[0] = *(const float4*)&As[kk][ty * TM];
            *(float4*)&a[4] = *(const float4*)&As[kk][ty * TM + 4];
            *(float4*)&b[0] = *(const float4*)&Ws[kk][tx * TN];
            *(float4*)&b[4] = *(const float4*)&Ws[kk][tx * TN + 4];
            #pragma unroll
            for (int i = 0; i < TM; i++)
                #pragma unroll
                for (int j = 0; j < TN; j++)
                    acc[i][j] = fmaf(a[i], b[j], acc[i][j]);
        }
        __syncthreads();
    }

    #pragma unroll
    for (int i = 0; i < TM; i++) {
        const int m = bm + ty * TM + i;
        #pragma unroll
        for (int j = 0; j < TN; j += 4) {
            const int n = bn + tx * TN + j;
            float4 o;
            o.x = acc[i][j + 0] + bias[n + 0];
            o.y = acc[i][j + 1] + bias[n + 1];
            o.z = acc[i][j + 2] + bias[n + 2];
            o.w = acc[i][j + 3] + bias[n + 3];
            *(float4*)(C + (size_t)m * N + n) = o;
        }
    }
}

// ---------------------------------------------------------------------------
// Scores: attn[b,h,q,k] = (Q_h[q,:] . K_h[k,:]) / 8 + beta*sim[b,q,k], masked.
// Per block: 64 (q) x 64 (k) tile, head-dim 64 in 4 chunks of 16.
// ---------------------------------------------------------------------------
__global__ __launch_bounds__(256) void scores_kernel(
    const float* __restrict__ sim, const int* __restrict__ amask,
    const float* __restrict__ beta_p, float* __restrict__ attn)
{
    const float* Q  = g_buf;
    const float* Kh = g_buf + CHUNK;

    constexpr int BQ = 64, BKt = 64, BD = 16;
    __shared__ float Qs[BD][BQ + 4];
    __shared__ float Ks[BD][BKt + 4];

    const int bh = blockIdx.z, b = bh >> 4, h = bh & 15;
    const int q0 = blockIdx.y * BQ, k0 = blockIdx.x * BKt;
    const int tid = threadIdx.x, tx = tid & 15, ty = tid >> 4;

    const int lrow = tid >> 2;        // 0..63
    const int lcol = (tid & 3) * 4;   // 0,4,8,12
    const size_t qbase = ((size_t)b * Sc + q0 + lrow) * HIDc + h * HDc + lcol;
    const size_t kbase = ((size_t)b * Sc + k0 + lrow) * HIDc + h * HDc + lcol;

    float acc[4][4] = {};

    #pragma unroll
    for (int d0 = 0; d0 < HDc; d0 += BD) {
        float4 qv = *(const float4*)(Q + qbase + d0);
        float4 kv = *(const float4*)(Kh + kbase + d0);
        Qs[lcol + 0][lrow] = qv.x; Qs[lcol + 1][lrow] = qv.y;
        Qs[lcol + 2][lrow] = qv.z; Qs[lcol + 3][lrow] = qv.w;
        Ks[lcol + 0][lrow] = kv.x; Ks[lcol + 1][lrow] = kv.y;
        Ks[lcol + 2][lrow] = kv.z; Ks[lcol + 3][lrow] = kv.w;
        __syncthreads();
        #pragma unroll
        for (int kk = 0; kk < BD; kk++) {
            float a[4], c[4];
            *(float4*)a = *(const float4*)&Qs[kk][ty * 4];
            *(float4*)c = *(const float4*)&Ks[kk][tx * 4];
            #pragma unroll
            for (int i = 0; i < 4; i++)
                #pragma unroll
                for (int j = 0; j < 4; j++)
                    acc[i][j] = fmaf(a[i], c[j], acc[i][j]);
        }
        __syncthreads();
    }

    const float beta = *beta_p;
    const float scale = 0.125f;  // 1/sqrt(64)
    const int4 m4 = *(const int4*)(amask + (size_t)b * Sc + k0 + tx * 4);

    #pragma unroll
    for (int i = 0; i < 4; i++) {
        const int q = q0 + ty * 4 + i;
        const float4 sv = *(const float4*)(sim + ((size_t)b * Sc + q) * Sc + k0 + tx * 4);
        float4 o;
        o.x = (m4.x == 0) ? -1e30f : fmaf(beta, sv.x, acc[i][0] * scale);
        o.y = (m4.y == 0) ? -1e30f : fmaf(beta, sv.y, acc[i][1] * scale);
        o.z = (m4.z == 0) ? -1e30f : fmaf(beta, sv.z, acc[i][2] * scale);
        o.w = (m4.w == 0) ? -1e30f : fmaf(beta, sv.w, acc[i][3] * scale);
        *(float4*)(attn + ((size_t)bh * Sc + q) * Sc + k0 + tx * 4) = o;
    }
}

// ---------------------------------------------------------------------------
// Row softmax in place over the last dim (2048). One block per row.
// ---------------------------------------------------------------------------
__global__ __launch_bounds__(256) void softmax_kernel(float* __restrict__ attn)
{
    float* p = attn + (size_t)blockIdx.x * Sc;
    const int tid = threadIdx.x;
    const int w = tid >> 5, l = tid & 31;

    float v[8];
    float4 v0 = *(const float4*)(p + tid * 4);
    float4 v1 = *(const float4*)(p + 1024 + tid * 4);
    v[0] = v0.x; v[1] = v0.y; v[2] = v0.z; v[3] = v0.w;
    v[4] = v1.x; v[5] = v1.y; v[6] = v1.z; v[7] = v1.w;

    float mx = v[0];
    #pragma unroll
    for (int i = 1; i < 8; i++) mx = fmaxf(mx, v[i]);
    #pragma unroll
    for (int o = 16; o; o >>= 1) mx = fmaxf(mx, __shfl_xor_sync(0xffffffffu, mx, o));

    __shared__ float sm_max[8];
    __shared__ float sm_sum[8];
    if (l == 0) sm_max[w] = mx;
    __syncthreads();
    if (tid == 0) {
        float m = sm_max[0];
        #pragma unroll
        for (int i = 1; i < 8; i++) m = fmaxf(m, sm_max[i]);
        sm_max[0] = m;
    }
    __syncthreads();
    mx = sm_max[0];

    float s = 0.0f;
    #pragma unroll
    for (int i = 0; i < 8; i++) { v[i] = expf(v[i] - mx); s += v[i]; }
    #pragma unroll
    for (int o = 16; o; o >>= 1) s += __shfl_xor_sync(0xffffffffu, s, o);
    if (l == 0) sm_sum[w] = s;
    __syncthreads();
    if (tid == 0) {
        float t = sm_sum[0];
        #pragma unroll
        for (int i = 1; i < 8; i++) t += sm_sum[i];
        sm_sum[0] = t;
    }
    __syncthreads();
    const float inv = 1.0f / sm_sum[0];

    float4 o0, o1;
    o0.x = v[0] * inv; o0.y = v[1] * inv; o0.z = v[2] * inv; o0.w = v[3] * inv;
    o1.x = v[4] * inv; o1.y = v[5] * inv; o1.z = v[6] * inv; o1.w = v[7] * inv;
    *(float4*)(p + tid * 4) = o0;
    *(float4*)(p + 1024 + tid * 4) = o1;
}

// ---------------------------------------------------------------------------
// AV: ctx[b,q,h*64+d] = sum_k attn[b,h,q,k] * V[b,k,h*64+d]
// Per block: 64 (q) x 64 (d, full head) tile, K in chunks of 32.
// ---------------------------------------------------------------------------
__global__ __launch_bounds__(256) void av_kernel(const float* __restrict__ attn)
{
    const float* V = g_buf + 2 * CHUNK;
    float*     ctx = g_buf + 3 * CHUNK;

    constexpr int BQ = 64, BKk = 32;
    __shared__ float As[BKk][BQ + 4];
    __shared__ float Vs[BKk][HDc + 4];

    const int bh = blockIdx.z, b = bh >> 4, h = bh & 15;
    const int q0 = blockIdx.x * BQ;
    const int tid = threadIdx.x, tx = tid & 15, ty = tid >> 4;

    const float* Abase = attn + ((size_t)bh * Sc + q0) * Sc;
    const float* Vbase = V + (size_t)b * Sc * HIDc + h * HDc;

    float acc[4][4] = {};

    for (int k0 = 0; k0 < Sc; k0 += BKk) {
        #pragma unroll
        for (int lL = 0; lL < 2; lL++) {
            const int e = tid + lL * 256;
            const int ar = e >> 3, ac = (e & 7) * 4;       // A tile: 64 rows x 32 cols
            float4 av = *(const float4*)(Abase + (size_t)ar * Sc + k0 + ac);
            As[ac + 0][ar] = av.x; As[ac + 1][ar] = av.y;
            As[ac + 2][ar] = av.z; As[ac + 3][ar] = av.w;
            const int vr = e >> 4, vc = (e & 15) * 4;      // V tile: 32 rows x 64 cols
            *(float4*)&Vs[vr][vc] =
                *(const float4*)(Vbase + (size_t)(k0 + vr) * HIDc + vc);
        }
        __syncthreads();
        #pragma unroll
        for (int kk = 0; kk < BKk; kk++) {
            float a[4], c[4];
            *(float4*)a = *(const float4*)&As[kk][ty * 4];
            *(float4*)c = *(const float4*)&Vs[kk][tx * 4];
            #pragma unroll
            for (int i = 0; i < 4; i++)
                #pragma unroll
                for (int j = 0; j < 4; j++)
                    acc[i][j] = fmaf(a[i], c[j], acc[i][j]);
        }
        __syncthreads();
    }

    #pragma unroll
    for (int i = 0; i < 4; i++) {
        const int q = q0 + ty * 4 + i;
        float4 o;
        o.x = acc[i][0]; o.y = acc[i][1]; o.z = acc[i][2]; o.w = acc[i][3];
        *(float4*)(ctx + ((size_t)b * Sc + q) * HIDc + h * HDc + tx * 4) = o;
    }
}

// ---------------------------------------------------------------------------
// Launcher
// ---------------------------------------------------------------------------
extern "C" void kernel_launch(void* const* d_in, const int* in_sizes, int n_in,
                              void* d_out, int out_size)
{
    const float* query = (const float*)d_in[0];
    const float* key   = (const float*)d_in[1];
    const float* value = (const float*)d_in[2];
    const int*   amask = (const int*)  d_in[3];
    const float* sim   = (const float*)d_in[4];
    const float* Wq    = (const float*)d_in[5];
    const float* bq    = (const float*)d_in[6];
    const float* Wk    = (const float*)d_in[7];
    const float* bk    = (const float*)d_in[8];
    const float* Wv    = (const float*)d_in[9];
    const float* bv    = (const float*)d_in[10];
    const float* Wo    = (const float*)d_in[11];
    const float* bo    = (const float*)d_in[12];
    const float* beta  = (const float*)d_in[13];

    float* out  = (float*)d_out;
    float* attn = out + CHUNK;   // attention_weights region [B,NH,S,S]

    dim3 gp(HIDc / 128, Mtot / 128);                  // (8, 32)
    sgemm_nt_bias<<<gp, 256>>>(query, -1, Wq, bq, nullptr, 0, Mtot, HIDc, HIDc);
    sgemm_nt_bias<<<gp, 256>>>(key,   -1, Wk, bk, nullptr, 1, Mtot, HIDc, HIDc);
    sgemm_nt_bias<<<gp, 256>>>(value, -1, Wv, bv, nullptr, 2, Mtot, HIDc, HIDc);

    dim3 gs(Sc / 64, Sc / 64, Bc * NHc);              // (32, 32, 32)
    scores_kernel<<<gs, 256>>>(sim, amask, beta, attn);

    softmax_kernel<<<Bc * NHc * Sc, 256>>>(attn);

    dim3 ga(Sc / 64, 1, Bc * NHc);                    // (32, 1, 32)
    av_kernel<<<ga, 256>>>(attn);

    sgemm_nt_bias<<<gp, 256>>>(nullptr, 3, Wo, bo, out, -1, Mtot, HIDc, HIDc);
}